// round 4
// baseline (speedup 1.0000x reference)
#include <cuda_runtime.h>
#include <cstdint>

// ---------------------------------------------------------------------------
// CTC forward loss (sum reduction, zero_infinity) for B=32, T=1024, V=1024,
// L=256 (S = 2L+1 = 513).  Three kernels:
//   1) gather_kernel : compact emissions lp[b,t,labels[b,:]] and lp[b,t,0]
//                      into L2-friendly arrays, converted to log2 domain.
//   2) ctc_dp_kernel : one CTA per batch sample, alpha recursion over T with
//                      double-buffered smem, parity-split thread mapping.
//   3) reduce_kernel : deterministic fixed-order sum of per-sample losses.
// ---------------------------------------------------------------------------

#define MAX_B 32
#define MAX_T 1024
#define MAX_L 256

static __device__ float g_emc[(size_t)MAX_B * MAX_T * MAX_L]; // label emissions (log2)
static __device__ float g_emb[(size_t)MAX_B * MAX_T];         // blank emissions (log2)
static __device__ float g_loss[MAX_B];                        // per-sample loss

#define NEGV (-1e30f)
#define LOG2E 1.4426950408889634f
#define LN2   0.6931471805599453f

__device__ __forceinline__ float fast_exp2(float x) {
    float r;
    asm("ex2.approx.ftz.f32 %0, %1;" : "=f"(r) : "f"(x));
    return r;
}
__device__ __forceinline__ float fast_log2(float x) {
    float r;
    asm("lg2.approx.f32 %0, %1;" : "=f"(r) : "f"(x));
    return r;
}

// ---------------------------------------------------------------------------
// Kernel 1: emission gather / compaction.  grid = B*T blocks, 256 threads.
// ---------------------------------------------------------------------------
__global__ void gather_kernel(const float* __restrict__ lp,
                              const int* __restrict__ labels,
                              int Tn, int Vn, int Ln) {
    const int bt = blockIdx.x;            // b*Tn + t
    const int b  = bt / Tn;
    const float* row = lp + (size_t)bt * Vn;
    for (int j = threadIdx.x; j < Ln; j += blockDim.x) {
        int lab = labels[b * Ln + j];
        g_emc[(size_t)bt * Ln + j] = row[lab] * LOG2E;
    }
    if (threadIdx.x == 0) {
        g_emb[bt] = row[0] * LOG2E;
    }
}

// ---------------------------------------------------------------------------
// Kernel 2: CTC alpha recursion.  grid = B, block = 544 threads (17 warps).
// Thread mapping (parity split so MUFU load is uniform within a warp):
//   tid in [0, Ln+1)        -> even state s = 2*tid       (blank states)
//   tid in [Ln+1, 2Ln+1)    -> odd  state s = 2*(tid-Ln-1)+1  (label states)
// alpha stored in smem double buffer indexed by state s (+2 NEG padding).
// ---------------------------------------------------------------------------
__global__ __launch_bounds__(544, 1)
void ctc_dp_kernel(const int* __restrict__ labels,
                   const int* __restrict__ input_lens,
                   const int* __restrict__ label_lens,
                   int Tn, int Ln) {
    __shared__ float sm[2][2 + 2 * MAX_L + 2];   // [2][516]

    const int b   = blockIdx.x;
    const int tid = threadIdx.x;
    const int S   = 2 * Ln + 1;
    const int nEven = Ln + 1;

    const bool active = (tid < S);
    const bool even   = (tid < nEven);
    const int  i      = even ? tid : (tid - nEven);
    const int  s      = even ? (2 * i) : (2 * i + 1);
    const int  idx    = s + 2;

    const int Tb = input_lens[b];

    // skip transition allowed for odd state s=2i+1 iff i>0 and labels differ
    bool skip = false;
    if (active && !even && i > 0) {
        int li  = labels[b * Ln + i];
        int lim = labels[b * Ln + i - 1];
        skip = (li != lim);
    }

    const float* __restrict__ emc = g_emc + (size_t)b * Tn * Ln;
    const float* __restrict__ emb = g_emb + (size_t)b * Tn;

    // padding (states -2, -1) = NEG in both buffers
    if (tid < 2) { sm[0][tid] = NEGV; sm[1][tid] = NEGV; }

    // t = 0 init
    float a = NEGV;
    if (active) {
        if (s == 0)      a = emb[0];
        else if (s == 1) a = emc[0];
        sm[0][idx] = a;
    }
    __syncthreads();

    // 2-deep register prefetch of emissions
    float em1 = 0.f, em2 = 0.f;
    if (active) {
        if (Tn > 1) em1 = even ? emb[1] : emc[(size_t)1 * Ln + i];
        if (Tn > 2) em2 = even ? emb[2] : emc[(size_t)2 * Ln + i];
    }

    int p = 0;
    for (int t = 1; t < Tn; ++t) {
        const float em = em1;
        em1 = em2;
        const int tp = t + 2;
        if (active && tp < Tn)
            em2 = even ? emb[tp] : emc[(size_t)tp * Ln + i];

        float anew = a;
        if (active) {
            const float a2 = sm[p][idx - 1];
            float r;
            if (even) {
                // 2-way logaddexp (base 2): 1 EX2 + 1 LG2
                const float m = fmaxf(a, a2);
                const float d = fminf(a, a2) - m;
                r = m + fast_log2(1.0f + fast_exp2(d));
            } else {
                // 3-way logaddexp (base 2): 3 EX2 + 1 LG2
                const float a3 = skip ? sm[p][idx - 2] : NEGV;
                const float m  = fmaxf(fmaxf(a, a2), a3);
                const float sum = fast_exp2(a - m) + fast_exp2(a2 - m)
                                + fast_exp2(a3 - m);
                r = m + fast_log2(sum);
            }
            const float cand = r + em;
            anew = (t < Tb) ? cand : a;      // freeze past input length
            sm[p ^ 1][idx] = anew;
        }
        __syncthreads();
        a = anew;
        p ^= 1;
    }

    if (tid == 0) {
        const int Lb = label_lens[b];
        const int sl = 2 * Lb;
        const float al = sm[p][sl + 2];
        const float ap = sm[p][sl + 1];
        const float m  = fmaxf(al, ap);
        const float d  = fminf(al, ap) - m;
        const float l2 = m + fast_log2(1.0f + fast_exp2(d));
        float loss = -l2 * LN2;
        if (loss > 1e29f) loss = 0.0f;       // zero_infinity
        g_loss[b] = loss;
    }
}

// ---------------------------------------------------------------------------
// Kernel 3: deterministic reduction of per-sample losses.
// ---------------------------------------------------------------------------
__global__ void reduce_kernel(float* __restrict__ out, int Bn) {
    if (threadIdx.x == 0 && blockIdx.x == 0) {
        float s = 0.0f;
        for (int b = 0; b < Bn; ++b) s += g_loss[b];
        out[0] = s;
    }
}

// ---------------------------------------------------------------------------
extern "C" void kernel_launch(void* const* d_in, const int* in_sizes, int n_in,
                              void* d_out, int out_size) {
    const float* lp        = (const float*)d_in[0]; // [B, T, V] log-probs
    const int*   labels    = (const int*)d_in[1];   // [B, L]
    const int*   ilens     = (const int*)d_in[2];   // [B]
    const int*   llens     = (const int*)d_in[3];   // [B]

    const int B = in_sizes[2];
    const int L = in_sizes[1] / B;
    const int T = 1024;                              // fixed dataset shape
    const int V = (int)((long long)in_sizes[0] / ((long long)B * T));

    if (B > MAX_B || L > MAX_L || T > MAX_T) return; // shape guard

    // 1) gather emissions
    gather_kernel<<<B * T, 256>>>(lp, labels, T, V, L);

    // 2) per-sample CTC DP: 513 states -> 544 threads (17 warps)
    const int S = 2 * L + 1;
    const int nthreads = ((S + 31) / 32) * 32;
    ctc_dp_kernel<<<B, nthreads>>>(labels, ilens, llens, T, L);

    // 3) deterministic sum into d_out
    reduce_kernel<<<1, 32>>>((float*)d_out, B);
}

// round 5
// speedup vs baseline: 2.0475x; 2.0475x over previous
#include <cuda_runtime.h>
#include <cstdint>

// ---------------------------------------------------------------------------
// CTC forward loss (sum, zero_infinity).  B=32, T=1024, V=1024, L=256, S=513.
//  1) gather2     : coalesced full-row load -> smem -> label gather (log2 dom)
//  2) ctc_dp      : one CTA/sample, 512 thr (16 warps), parity-pure warps,
//                   deep (16-step) register prefetch of emissions.
//  3) reduce      : deterministic fixed-order sum.
// ---------------------------------------------------------------------------

#define MAX_B 32
#define MAX_T 1024
#define MAX_L 256

static __device__ float g_emc[(size_t)MAX_B * MAX_T * MAX_L]; // label emis (log2)
static __device__ float g_emb[(size_t)MAX_B * MAX_T];         // blank emis (log2)
static __device__ float g_loss[MAX_B];

#define NEGV   (-1e30f)
#define SKIPB  (-2e30f)
#define LOG2E  1.4426950408889634f
#define LN2    0.6931471805599453f

__device__ __forceinline__ float fast_exp2(float x) {
    float r; asm("ex2.approx.ftz.f32 %0, %1;" : "=f"(r) : "f"(x)); return r;
}
__device__ __forceinline__ float fast_log2(float x) {
    float r; asm("lg2.approx.f32 %0, %1;" : "=f"(r) : "f"(x)); return r;
}

// ---------------------------------------------------------------------------
// Kernel 1: coalesced emission gather.  grid = B*T, block = 256.
// ---------------------------------------------------------------------------
__global__ __launch_bounds__(256)
void gather2(const float* __restrict__ lp, const int* __restrict__ labels,
             int Tn, int Vn, int Ln) {
    __shared__ float srow[1024];
    const int bt = blockIdx.x;
    const int b  = bt / Tn;
    const float4* r4 = (const float4*)(lp + (size_t)bt * Vn);
    for (int i = threadIdx.x; i < (Vn >> 2); i += blockDim.x)
        ((float4*)srow)[i] = r4[i];
    __syncthreads();
    for (int j = threadIdx.x; j < Ln; j += blockDim.x) {
        int lab = labels[b * Ln + j];
        g_emc[(size_t)bt * Ln + j] = srow[lab] * LOG2E;
    }
    if (threadIdx.x == 0) g_emb[bt] = srow[0] * LOG2E;
}

// ---------------------------------------------------------------------------
// Kernel 2: CTC alpha recursion.  grid = B, block = 512 (16 warps).
//   tid 0..255   -> even state s=2*tid (blank); thread 0 also folds s=512.
//   tid 256..511 -> odd  state s=2*(tid-256)+1 (label).
// smem alpha split by parity (stride-1 neighbor reads, conflict-free):
//   aE[p][1+i]  i=0..256  (i=256 = folded state 512)
//   aO[p][1+j]  j=0..255 ; aO[p][0] = NEG pad (state -1)
// ---------------------------------------------------------------------------
#define CH 16

__global__ __launch_bounds__(512, 1)
void ctc_dp(const int* __restrict__ labels,
            const int* __restrict__ input_lens,
            const int* __restrict__ label_lens,
            int Tn, int Ln) {
    __shared__ float aE[2][260];
    __shared__ float aO[2][260];

    const int b   = blockIdx.x;
    const int tid = threadIdx.x;
    const bool even = (tid < 256);
    const int  j    = even ? tid : (tid - 256);   // even: i index, odd: j index
    const bool fold = (tid == 0);                 // thread 0 also owns s = 512

    const int Tb = input_lens[b];

    // skip bias for odd states: 0 if transition allowed, -2e30 otherwise
    float skipBias = SKIPB;
    if (!even && j > 0) {
        int li  = labels[b * Ln + j];
        int lim = labels[b * Ln + j - 1];
        if (li != lim) skipBias = 0.0f;
    }

    // per-thread emission stream pointer
    const float* __restrict__ eptr =
        even ? (g_emb + (size_t)b * Tn)
             : (g_emc + (size_t)b * Tn * Ln + j);
    const long estride = even ? 1 : Ln;

    // padding init
    if (tid == 0) { aO[0][0] = NEGV; aO[1][0] = NEGV; }

    // t = 0 init
    float a;
    float a512 = NEGV;
    if (even) {
        a = (j == 0) ? eptr[0] : NEGV;      // s=0 gets blank emission
        aE[0][1 + j] = a;
        if (fold) aE[0][257] = a512;
    } else {
        a = (j == 0) ? eptr[0] : NEGV;      // s=1 gets label-0 emission
        aO[0][1 + j] = a;
    }
    __syncthreads();

    // deep prefetch: two 16-step register chunks
    float emA[CH], emB[CH];
#pragma unroll
    for (int k = 0; k < CH; ++k)
        emA[k] = (1 + k < Tn) ? eptr[(long)(1 + k) * estride] : 0.0f;
#pragma unroll
    for (int k = 0; k < CH; ++k)
        emB[k] = (1 + CH + k < Tn) ? eptr[(long)(1 + CH + k) * estride] : 0.0f;

    int p = 0;
    for (int base = 1; base < Tn; base += CH) {
#pragma unroll
        for (int k = 0; k < CH; ++k) {
            const int t = base + k;
            if (t >= Tn) break;             // uniform across block
            const float em = emA[k];
            const float* __restrict__ aEr = aE[p];
            const float* __restrict__ aOr = aO[p];
            float* __restrict__ aEw = aE[p ^ 1];
            float* __restrict__ aOw = aO[p ^ 1];

            float anew;
            if (even) {
                // 2-way logaddexp: a (self), aO[j] (state 2j-1)
                const float a2 = aOr[j];
                const float m  = fmaxf(a, a2);
                const float d  = fminf(a, a2) - m;
                const float r  = m + fast_log2(1.0f + fast_exp2(d));
                anew = (t < Tb) ? (r + em) : a;
                aEw[1 + j] = anew;
                if (fold) {                 // state 512: self + odd 511
                    const float b2 = aOr[256];
                    const float mf = fmaxf(a512, b2);
                    const float df = fminf(a512, b2) - mf;
                    const float rf = mf + fast_log2(1.0f + fast_exp2(df));
                    a512 = (t < Tb) ? (rf + em) : a512;
                    aEw[257] = a512;
                }
            } else {
                // 3-way: self, even 2j, odd 2j-1 (skip, biased)
                const float a2 = aEr[1 + j];
                const float a3 = aOr[j] + skipBias;
                const float m  = fmaxf(fmaxf(a, a2), a3);
                const float s  = fast_exp2(a - m) + fast_exp2(a2 - m)
                               + fast_exp2(a3 - m);
                const float r  = m + fast_log2(s);
                anew = (t < Tb) ? (r + em) : a;
                aOw[1 + j] = anew;
            }
            __syncthreads();
            a = anew;
            p ^= 1;
        }
        // rotate prefetch buffers, refill next chunk (>= 16 steps of slack)
#pragma unroll
        for (int k = 0; k < CH; ++k) emA[k] = emB[k];
        const int nb = base + 2 * CH;
#pragma unroll
        for (int k = 0; k < CH; ++k)
            emB[k] = (nb + k < Tn) ? eptr[(long)(nb + k) * estride] : 0.0f;
    }

    if (tid == 0) {
        const int Lb = label_lens[b];
        const float al = aE[p][1 + Lb];     // even state 2*Lb
        const float ap = aO[p][Lb];         // odd state 2*Lb-1 (idx 0 = NEG pad)
        const float m  = fmaxf(al, ap);
        const float d  = fminf(al, ap) - m;
        const float l2 = m + fast_log2(1.0f + fast_exp2(d));
        float loss = -l2 * LN2;
        if (loss > 1e29f) loss = 0.0f;      // zero_infinity
        g_loss[b] = loss;
    }
}

// ---------------------------------------------------------------------------
// Kernel 3: deterministic reduction.
// ---------------------------------------------------------------------------
__global__ void reduce_kernel(float* __restrict__ out, int Bn) {
    if (threadIdx.x == 0 && blockIdx.x == 0) {
        float s = 0.0f;
        for (int b = 0; b < Bn; ++b) s += g_loss[b];
        out[0] = s;
    }
}

// ---------------------------------------------------------------------------
extern "C" void kernel_launch(void* const* d_in, const int* in_sizes, int n_in,
                              void* d_out, int out_size) {
    const float* lp     = (const float*)d_in[0]; // [B,T,V]
    const int*   labels = (const int*)d_in[1];   // [B,L]
    const int*   ilens  = (const int*)d_in[2];   // [B]
    const int*   llens  = (const int*)d_in[3];   // [B]

    const int B = in_sizes[2];
    const int L = in_sizes[1] / B;
    const int T = 1024;                          // fixed dataset shape
    const int V = (int)((long long)in_sizes[0] / ((long long)B * T));

    if (B > MAX_B || L != 256 || T > MAX_T || V > 1024) return;

    gather2<<<B * T, 256>>>(lp, labels, T, V, L);
    ctc_dp<<<B, 512>>>(labels, ilens, llens, T, L);
    reduce_kernel<<<1, 32>>>((float*)d_out, B);
}